// round 1
// baseline (speedup 1.0000x reference)
#include <cuda_runtime.h>
#include <math.h>

// Problem constants (fixed by the reference)
#define Bb 4
#define Tt 2048
#define Cc 1024
#define Hh 16
#define Dd 64
#define NHALF 32   // Dd/2

// ---------------- scratch (device globals; no allocs allowed) ----------------
__device__ float g_qkv[(size_t)Bb * Tt * 3 * Cc];      // [b,t,3,h,d] raw qkv+bias
__device__ float g_q  [(size_t)Bb * Hh * Tt * Dd];     // [b,h,t,d] rope'd
__device__ float g_k  [(size_t)Bb * Hh * Tt * Dd];
__device__ float g_v  [(size_t)Bb * Hh * Tt * Dd];
__device__ float g_ao [(size_t)Bb * Tt * Cc];          // attention out [b,t,h*d]
__device__ float g_cs [Tt * NHALF * 2];                // interleaved cos,sin

// ---------------- RoPE table ----------------
__global__ void rope_table_kernel(float* cs) {
    int idx = blockIdx.x * blockDim.x + threadIdx.x;
    if (idx >= Tt * NHALF) return;
    int t = idx >> 5;
    int j = idx & 31;
    double freq  = pow(40.0, (double)j / 31.0);                    // MIN=1, MAX=40
    double theta = 2.0 * 3.14159265358979323846 * ((double)t / (double)Tt) * freq;
    cs[idx * 2 + 0] = (float)cos(theta);
    cs[idx * 2 + 1] = (float)sin(theta);
}

// ---------------- SGEMM: C[M,N] = A[M,K] @ B[N,K]^T + bias[N] ----------------
// BM=128, BN=128, BK=16, 256 threads, 8x8 per thread.
__global__ void __launch_bounds__(256) sgemm_nt_bias(
    const float* __restrict__ A, const float* __restrict__ B,
    const float* __restrict__ bias, float* __restrict__ C,
    int M, int N, int K)
{
    __shared__ float As[16][128];
    __shared__ float Bs[16][128];

    const int tid = threadIdx.x;
    const int ty  = tid >> 4;      // 0..15
    const int tx  = tid & 15;      // 0..15
    const int bm  = blockIdx.y * 128;
    const int bn  = blockIdx.x * 128;

    const float* Ab = A + (size_t)bm * K;
    const float* Bb2 = B + (size_t)bn * K;

    float acc[8][8];
#pragma unroll
    for (int i = 0; i < 8; i++)
#pragma unroll
        for (int j = 0; j < 8; j++) acc[i][j] = 0.f;

    for (int k0 = 0; k0 < K; k0 += 16) {
#pragma unroll
        for (int i = 0; i < 2; i++) {
            int li  = tid + i * 256;      // 0..511
            int row = li >> 2;            // 0..127
            int c4  = li & 3;             // float4 slot within BK
            float4 a = *(const float4*)(Ab + (size_t)row * K + k0 + c4 * 4);
            As[c4 * 4 + 0][row] = a.x;
            As[c4 * 4 + 1][row] = a.y;
            As[c4 * 4 + 2][row] = a.z;
            As[c4 * 4 + 3][row] = a.w;
            float4 b = *(const float4*)(Bb2 + (size_t)row * K + k0 + c4 * 4);
            Bs[c4 * 4 + 0][row] = b.x;
            Bs[c4 * 4 + 1][row] = b.y;
            Bs[c4 * 4 + 2][row] = b.z;
            Bs[c4 * 4 + 3][row] = b.w;
        }
        __syncthreads();
#pragma unroll
        for (int kk = 0; kk < 16; kk++) {
            float ar[8], br[8];
            *(float4*)&ar[0] = *(const float4*)&As[kk][ty * 8];
            *(float4*)&ar[4] = *(const float4*)&As[kk][ty * 8 + 4];
            *(float4*)&br[0] = *(const float4*)&Bs[kk][tx * 8];
            *(float4*)&br[4] = *(const float4*)&Bs[kk][tx * 8 + 4];
#pragma unroll
            for (int i = 0; i < 8; i++)
#pragma unroll
                for (int j = 0; j < 8; j++)
                    acc[i][j] = fmaf(ar[i], br[j], acc[i][j]);
        }
        __syncthreads();
    }

#pragma unroll
    for (int i = 0; i < 8; i++) {
        int row = bm + ty * 8 + i;
#pragma unroll
        for (int j = 0; j < 8; j += 4) {
            int col = bn + tx * 8 + j;
            float4 r;
            r.x = acc[i][j + 0] + bias[col + 0];
            r.y = acc[i][j + 1] + bias[col + 1];
            r.z = acc[i][j + 2] + bias[col + 2];
            r.w = acc[i][j + 3] + bias[col + 3];
            *(float4*)(C + (size_t)row * N + col) = r;
        }
    }
}

// ---------------- RoPE apply + scatter to [b,h,t,d] ----------------
// one thread per (b,t,h,j), j in [0,32): handles q pair, k pair, v pair
__global__ void rope_scatter_kernel(const float* __restrict__ QKV,
                                    const float* __restrict__ cs,
                                    float* __restrict__ Q,
                                    float* __restrict__ K,
                                    float* __restrict__ V)
{
    int idx = blockIdx.x * blockDim.x + threadIdx.x;
    if (idx >= Bb * Tt * Hh * NHALF) return;
    int j = idx & 31;
    int h = (idx >> 5) & 15;
    int t = (idx >> 9) & 2047;
    int b = idx >> 20;

    float co = cs[(t * 32 + j) * 2 + 0];
    float si = cs[(t * 32 + j) * 2 + 1];

    size_t base = ((size_t)(b * Tt + t)) * (3 * Cc) + h * Dd + j;  // s=0 slot
    float q1 = QKV[base];
    float q2 = QKV[base + 32];
    float k1 = QKV[base + Cc];
    float k2 = QKV[base + Cc + 32];
    float v1 = QKV[base + 2 * Cc];
    float v2 = QKV[base + 2 * Cc + 32];

    size_t ob = ((size_t)((b * Hh + h) * Tt + t)) * Dd + j;
    Q[ob]      = q1 * co - q2 * si;
    Q[ob + 32] = q1 * si + q2 * co;
    K[ob]      = k1 * co - k2 * si;
    K[ob + 32] = k1 * si + k2 * co;
    V[ob]      = v1;
    V[ob + 32] = v2;
}

// ---------------- Flash attention, fp32, 64q x 64k tiles ----------------
// grid: (Tt/64, Bb*Hh), block 256 (16x16 threads, 4x4 microtile)
// dynamic smem: qT[64][64] | kT/pT alias [64][64] | v[64][64]  = 48 KB
__global__ void __launch_bounds__(256) flash_attn_kernel(
    const float* __restrict__ Qg, const float* __restrict__ Kg,
    const float* __restrict__ Vg, float* __restrict__ AO)
{
    extern __shared__ float sm[];
    float (*qT)[64] = (float(*)[64])(sm);          // qT[dd][row], pre-scaled
    float (*kp)[64] = (float(*)[64])(sm + 4096);   // kT[dd][col]  <->  pT[col][row]
    float (*vs)[64] = (float(*)[64])(sm + 8192);   // v[col][dd]

    const int tid = threadIdx.x;
    const int ty  = tid >> 4;
    const int tx  = tid & 15;
    const int qt  = blockIdx.x;    // query tile
    const int bh  = blockIdx.y;    // b*H + h
    const int b   = bh >> 4;
    const int h   = bh & 15;

    const size_t head_off = (size_t)bh * Tt * Dd;
    const float* Qh = Qg + head_off + (size_t)qt * 64 * Dd;
    const float* Kh = Kg + head_off;
    const float* Vh = Vg + head_off;

    // load Q tile transposed + pre-scale by 1/sqrt(64)
    {
        int row = tid >> 2;
        int db  = (tid & 3) * 16;
#pragma unroll
        for (int u = 0; u < 4; u++) {
            float4 qv = *(const float4*)(Qh + (size_t)row * Dd + db + u * 4);
            qT[db + u * 4 + 0][row] = qv.x * 0.125f;
            qT[db + u * 4 + 1][row] = qv.y * 0.125f;
            qT[db + u * 4 + 2][row] = qv.z * 0.125f;
            qT[db + u * 4 + 3][row] = qv.w * 0.125f;
        }
    }

    float o[4][4];
    float m_i[4], l_i[4];
#pragma unroll
    for (int r = 0; r < 4; r++) {
        m_i[r] = -1e30f; l_i[r] = 0.f;
#pragma unroll
        for (int c = 0; c < 4; c++) o[r][c] = 0.f;
    }

    for (int kt = 0; kt < Tt / 64; kt++) {
        __syncthreads();  // prev PV reads of kp/vs done; qT writes visible (iter 0)
        {
            int row = tid >> 2;
            int db  = (tid & 3) * 16;
            const float* kr = Kh + (size_t)(kt * 64 + row) * Dd;
            const float* vr = Vh + (size_t)(kt * 64 + row) * Dd;
#pragma unroll
            for (int u = 0; u < 4; u++) {
                float4 kv = *(const float4*)(kr + db + u * 4);
                kp[db + u * 4 + 0][row] = kv.x;
                kp[db + u * 4 + 1][row] = kv.y;
                kp[db + u * 4 + 2][row] = kv.z;
                kp[db + u * 4 + 3][row] = kv.w;
                float4 vv = *(const float4*)(vr + db + u * 4);
                *(float4*)&vs[row][db + u * 4] = vv;
            }
        }
        __syncthreads();

        // S = (Q * scale) @ K^T
        float s[4][4];
#pragma unroll
        for (int r = 0; r < 4; r++)
#pragma unroll
            for (int c = 0; c < 4; c++) s[r][c] = 0.f;
#pragma unroll 16
        for (int kk = 0; kk < 64; kk++) {
            float4 aq = *(const float4*)&qT[kk][ty * 4];
            float4 bk = *(const float4*)&kp[kk][tx * 4];
            float a0[4] = {aq.x, aq.y, aq.z, aq.w};
            float b0[4] = {bk.x, bk.y, bk.z, bk.w};
#pragma unroll
            for (int r = 0; r < 4; r++)
#pragma unroll
                for (int c = 0; c < 4; c++)
                    s[r][c] = fmaf(a0[r], b0[c], s[r][c]);
        }

        // online softmax (row reductions across the 16 tx lanes of each half-warp)
#pragma unroll
        for (int r = 0; r < 4; r++) {
            float mx = fmaxf(fmaxf(s[r][0], s[r][1]), fmaxf(s[r][2], s[r][3]));
#pragma unroll
            for (int msk = 1; msk < 16; msk <<= 1)
                mx = fmaxf(mx, __shfl_xor_sync(0xffffffffu, mx, msk));
            float m_new = fmaxf(m_i[r], mx);
            float corr  = expf(m_i[r] - m_new);
            float sum = 0.f;
#pragma unroll
            for (int c = 0; c < 4; c++) { s[r][c] = expf(s[r][c] - m_new); sum += s[r][c]; }
#pragma unroll
            for (int msk = 1; msk < 16; msk <<= 1)
                sum += __shfl_xor_sync(0xffffffffu, sum, msk);
            l_i[r] = l_i[r] * corr + sum;
            m_i[r] = m_new;
#pragma unroll
            for (int c = 0; c < 4; c++) o[r][c] *= corr;
        }

        __syncthreads();  // everyone done reading kT before overwriting with pT
        // store P transposed: pT[col][row]
#pragma unroll
        for (int r = 0; r < 4; r++)
#pragma unroll
            for (int c = 0; c < 4; c++)
                kp[tx * 4 + c][ty * 4 + r] = s[r][c];
        __syncthreads();

        // O += P @ V
#pragma unroll 8
        for (int j = 0; j < 64; j++) {
            float4 pv4 = *(const float4*)&kp[j][ty * 4];   // p[rows][j], broadcast
            float4 vv4 = *(const float4*)&vs[j][tx * 4];
            float p0[4] = {pv4.x, pv4.y, pv4.z, pv4.w};
            float v0[4] = {vv4.x, vv4.y, vv4.z, vv4.w};
#pragma unroll
            for (int r = 0; r < 4; r++)
#pragma unroll
                for (int c = 0; c < 4; c++)
                    o[r][c] = fmaf(p0[r], v0[c], o[r][c]);
        }
    }

    // write [b, t, h*64 + dd]
#pragma unroll
    for (int r = 0; r < 4; r++) {
        int t = qt * 64 + ty * 4 + r;
        float inv = 1.f / l_i[r];
        float4 ov;
        ov.x = o[r][0] * inv; ov.y = o[r][1] * inv;
        ov.z = o[r][2] * inv; ov.w = o[r][3] * inv;
        *(float4*)(AO + (size_t)(b * Tt + t) * Cc + h * Dd + tx * 4) = ov;
    }
}

// ---------------- launch ----------------
extern "C" void kernel_launch(void* const* d_in, const int* in_sizes, int n_in,
                              void* d_out, int out_size)
{
    const float* x      = (const float*)d_in[0];   // [4,2048,1024]
    const float* qkv_w  = (const float*)d_in[1];   // [3072,1024]
    const float* qkv_b  = (const float*)d_in[2];   // [3072]
    const float* proj_w = (const float*)d_in[3];   // [1024,1024]
    const float* proj_b = (const float*)d_in[4];   // [1024]
    float* out = (float*)d_out;                    // [4,2048,1024]

    float *p_qkv, *p_q, *p_k, *p_v, *p_ao, *p_cs;
    cudaGetSymbolAddress((void**)&p_qkv, g_qkv);
    cudaGetSymbolAddress((void**)&p_q,   g_q);
    cudaGetSymbolAddress((void**)&p_k,   g_k);
    cudaGetSymbolAddress((void**)&p_v,   g_v);
    cudaGetSymbolAddress((void**)&p_ao,  g_ao);
    cudaGetSymbolAddress((void**)&p_cs,  g_cs);

    // 1) RoPE table
    rope_table_kernel<<<(Tt * NHALF + 255) / 256, 256>>>(p_cs);

    // 2) QKV GEMM: [8192,3072] = x[8192,1024] @ qkv_w^T + qkv_b
    {
        dim3 grid(3 * Cc / 128, (Bb * Tt) / 128);
        sgemm_nt_bias<<<grid, 256>>>(x, qkv_w, qkv_b, p_qkv,
                                     Bb * Tt, 3 * Cc, Cc);
    }

    // 3) RoPE + scatter to [b,h,t,d]
    rope_scatter_kernel<<<(Bb * Tt * Hh * NHALF) / 256, 256>>>(
        p_qkv, p_cs, p_q, p_k, p_v);

    // 4) flash attention
    {
        dim3 grid(Tt / 64, Bb * Hh);
        flash_attn_kernel<<<grid, 256, 48 * 1024>>>(p_q, p_k, p_v, p_ao);
    }

    // 5) proj GEMM: out[8192,1024] = ao @ proj_w^T + proj_b
    {
        dim3 grid(Cc / 128, (Bb * Tt) / 128);
        sgemm_nt_bias<<<grid, 256>>>(p_ao, proj_w, proj_b, out,
                                     Bb * Tt, Cc, Cc);
    }
}

// round 2
// speedup vs baseline: 2.3088x; 2.3088x over previous
#include <cuda_runtime.h>
#include <math.h>
#include <stdint.h>

// Problem constants (fixed by the reference)
#define Bb 4
#define Tt 2048
#define Cc 1024
#define Hh 16
#define Dd 64
#define NHALF 32   // Dd/2

// ---------------- scratch (device globals; no allocs allowed) ----------------
__device__ float g_qkv[(size_t)Bb * Tt * 3 * Cc];      // [b,t,3,h,d] raw qkv+bias
__device__ float g_q  [(size_t)Bb * Hh * Tt * Dd];     // [b,h,t,d] rope'd
__device__ float g_k  [(size_t)Bb * Hh * Tt * Dd];
__device__ float g_v  [(size_t)Bb * Hh * Tt * Dd];
__device__ float g_ao [(size_t)Bb * Tt * Cc];          // attention out [b,t,h*d]
__device__ float g_cs [Tt * NHALF * 2];                // interleaved cos,sin

// ---------------- helpers ----------------
__device__ __forceinline__ uint32_t f2tf32(float f) {
    uint32_t r;
    asm("cvt.rna.tf32.f32 %0, %1;" : "=r"(r) : "f"(f));
    return r;
}

// D = A(16x8) * B(8x8) + C, tf32 inputs, fp32 accum.
__device__ __forceinline__ void mma_tf32(float4& d,
    uint32_t a0, uint32_t a1, uint32_t a2, uint32_t a3,
    uint32_t b0, uint32_t b1)
{
    asm volatile(
        "mma.sync.aligned.m16n8k8.row.col.f32.tf32.tf32.f32 "
        "{%0,%1,%2,%3}, {%4,%5,%6,%7}, {%8,%9}, {%0,%1,%2,%3};\n"
        : "+f"(d.x), "+f"(d.y), "+f"(d.z), "+f"(d.w)
        : "r"(a0), "r"(a1), "r"(a2), "r"(a3), "r"(b0), "r"(b1));
}

// ---------------- RoPE table ----------------
__global__ void rope_table_kernel(float* cs) {
    int idx = blockIdx.x * blockDim.x + threadIdx.x;
    if (idx >= Tt * NHALF) return;
    int t = idx >> 5;
    int j = idx & 31;
    double freq  = pow(40.0, (double)j / 31.0);                    // MIN=1, MAX=40
    double theta = 2.0 * 3.14159265358979323846 * ((double)t / (double)Tt) * freq;
    cs[idx * 2 + 0] = (float)cos(theta);
    cs[idx * 2 + 1] = (float)sin(theta);
}

// ---------------- tf32 MMA GEMM: C[M,N] = A[M,K] @ B[N,K]^T + bias[N] ----------------
// BM=128, BN=128, BK=16. 256 threads = 8 warps (2x4). Warp tile 64x32.
// smem layout [row][k] with stride 20 words -> bank(frag) = 4*gid + tig = lane (conflict-free)
__global__ void __launch_bounds__(256, 2) mma_gemm_nt_bias(
    const float* __restrict__ A, const float* __restrict__ B,
    const float* __restrict__ bias, float* __restrict__ C,
    int M, int N, int K)
{
    __shared__ uint32_t As[128][20];
    __shared__ uint32_t Bs[128][20];

    const int tid  = threadIdx.x;
    const int lane = tid & 31;
    const int warp = tid >> 5;
    const int wr   = warp >> 2;         // 0..1
    const int wc   = warp & 3;          // 0..3
    const int gid  = lane >> 2;         // 0..7
    const int tig  = lane & 3;          // 0..3
    const int bm   = blockIdx.y * 128;
    const int bn   = blockIdx.x * 128;

    float4 acc[4][4];
#pragma unroll
    for (int i = 0; i < 4; i++)
#pragma unroll
        for (int j = 0; j < 4; j++) acc[i][j] = make_float4(0.f, 0.f, 0.f, 0.f);

    const int lrow = tid >> 2;          // 0..63
    const int lkc  = (tid & 3) * 4;     // 0,4,8,12
    const float* Ap0 = A + (size_t)(bm + lrow) * K + lkc;
    const float* Ap1 = A + (size_t)(bm + lrow + 64) * K + lkc;
    const float* Bp0 = B + (size_t)(bn + lrow) * K + lkc;
    const float* Bp1 = B + (size_t)(bn + lrow + 64) * K + lkc;

    for (int k0 = 0; k0 < K; k0 += 16) {
        float4 a0 = *(const float4*)(Ap0 + k0);
        float4 a1 = *(const float4*)(Ap1 + k0);
        float4 b0 = *(const float4*)(Bp0 + k0);
        float4 b1 = *(const float4*)(Bp1 + k0);
        {
            uint4 t0 = make_uint4(f2tf32(a0.x), f2tf32(a0.y), f2tf32(a0.z), f2tf32(a0.w));
            uint4 t1 = make_uint4(f2tf32(a1.x), f2tf32(a1.y), f2tf32(a1.z), f2tf32(a1.w));
            *(uint4*)&As[lrow][lkc]      = t0;
            *(uint4*)&As[lrow + 64][lkc] = t1;
            uint4 t2 = make_uint4(f2tf32(b0.x), f2tf32(b0.y), f2tf32(b0.z), f2tf32(b0.w));
            uint4 t3 = make_uint4(f2tf32(b1.x), f2tf32(b1.y), f2tf32(b1.z), f2tf32(b1.w));
            *(uint4*)&Bs[lrow][lkc]      = t2;
            *(uint4*)&Bs[lrow + 64][lkc] = t3;
        }
        __syncthreads();

#pragma unroll
        for (int ks = 0; ks < 2; ks++) {
            const int kb = ks * 8;
            uint32_t afr[4][4];
#pragma unroll
            for (int mt = 0; mt < 4; mt++) {
                int r0 = wr * 64 + mt * 16;
                afr[mt][0] = As[r0 + gid][kb + tig];
                afr[mt][1] = As[r0 + gid + 8][kb + tig];
                afr[mt][2] = As[r0 + gid][kb + tig + 4];
                afr[mt][3] = As[r0 + gid + 8][kb + tig + 4];
            }
            uint32_t bfr[4][2];
#pragma unroll
            for (int nt = 0; nt < 4; nt++) {
                int c0 = wc * 32 + nt * 8;
                bfr[nt][0] = Bs[c0 + gid][kb + tig];
                bfr[nt][1] = Bs[c0 + gid][kb + tig + 4];
            }
#pragma unroll
            for (int mt = 0; mt < 4; mt++)
#pragma unroll
                for (int nt = 0; nt < 4; nt++)
                    mma_tf32(acc[mt][nt],
                             afr[mt][0], afr[mt][1], afr[mt][2], afr[mt][3],
                             bfr[nt][0], bfr[nt][1]);
        }
        __syncthreads();
    }

    // epilogue: bias + store
#pragma unroll
    for (int nt = 0; nt < 4; nt++) {
        int c = bn + wc * 32 + nt * 8 + 2 * tig;
        float bx = bias[c];
        float by = bias[c + 1];
#pragma unroll
        for (int mt = 0; mt < 4; mt++) {
            int r0 = bm + wr * 64 + mt * 16 + gid;
            float2 lo = make_float2(acc[mt][nt].x + bx, acc[mt][nt].y + by);
            float2 hi = make_float2(acc[mt][nt].z + bx, acc[mt][nt].w + by);
            *(float2*)(C + (size_t)r0 * N + c)       = lo;
            *(float2*)(C + (size_t)(r0 + 8) * N + c) = hi;
        }
    }
}

// ---------------- RoPE apply + scatter to [b,h,t,d] ----------------
__global__ void rope_scatter_kernel(const float* __restrict__ QKV,
                                    const float* __restrict__ cs,
                                    float* __restrict__ Q,
                                    float* __restrict__ K,
                                    float* __restrict__ V)
{
    int idx = blockIdx.x * blockDim.x + threadIdx.x;
    if (idx >= Bb * Tt * Hh * NHALF) return;
    int j = idx & 31;
    int h = (idx >> 5) & 15;
    int t = (idx >> 9) & 2047;
    int b = idx >> 20;

    float co = cs[(t * 32 + j) * 2 + 0];
    float si = cs[(t * 32 + j) * 2 + 1];

    size_t base = ((size_t)(b * Tt + t)) * (3 * Cc) + h * Dd + j;  // s=0 slot
    float q1 = QKV[base];
    float q2 = QKV[base + 32];
    float k1 = QKV[base + Cc];
    float k2 = QKV[base + Cc + 32];
    float v1 = QKV[base + 2 * Cc];
    float v2 = QKV[base + 2 * Cc + 32];

    size_t ob = ((size_t)((b * Hh + h) * Tt + t)) * Dd + j;
    Q[ob]      = q1 * co - q2 * si;
    Q[ob + 32] = q1 * si + q2 * co;
    K[ob]      = k1 * co - k2 * si;
    K[ob + 32] = k1 * si + k2 * co;
    V[ob]      = v1;
    V[ob + 32] = v2;
}

// ---------------- Flash attention, tf32 mma, 64q x 64k tiles ----------------
// grid (32 qtiles, 64 bh), block 128 (4 warps). Each warp owns 16 q-rows.
// smem (dynamic, stride 68 words => frag bank = 4*gid+tig = lane, conflict-free):
//   Qs[64][68]  q row-major (pre-scaled by 1/8, tf32)
//   Kn[64][68]  k natural [key][d]   (aliased with Ps[64][68] = P [q][key])
//   Vt[64][68]  v transposed [d][key]
#define FS 68
__global__ void __launch_bounds__(128, 4) flash_mma_kernel(
    const float* __restrict__ Qg, const float* __restrict__ Kg,
    const float* __restrict__ Vg, float* __restrict__ AO)
{
    extern __shared__ uint32_t sm[];
    uint32_t (*Qs)[FS] = (uint32_t(*)[FS])sm;                  // 64*68
    uint32_t (*Kn)[FS] = (uint32_t(*)[FS])(sm + 64 * FS);      // aliased with Ps
    uint32_t (*Ps)[FS] = Kn;
    uint32_t (*Vt)[FS] = (uint32_t(*)[FS])(sm + 2 * 64 * FS);

    const int tid  = threadIdx.x;
    const int lane = tid & 31;
    const int warp = tid >> 5;
    const int gid  = lane >> 2;
    const int tig  = lane & 3;
    const int q0   = warp * 16;
    const int qt   = blockIdx.x;
    const int bh   = blockIdx.y;
    const int b    = bh >> 4;
    const int h    = bh & 15;

    const size_t head_off = (size_t)bh * Tt * Dd;
    const float* Qh = Qg + head_off + (size_t)qt * 64 * Dd;
    const float* Kh = Kg + head_off;
    const float* Vh = Vg + head_off;

    // load Q tile (row-major, pre-scale by 1/sqrt(64), cvt to tf32)
    {
        int row  = tid & 63;
        int dbas = (tid >> 6) * 32;
#pragma unroll
        for (int u = 0; u < 8; u++) {
            float4 qv = *(const float4*)(Qh + (size_t)row * Dd + dbas + u * 4);
            uint4 tv = make_uint4(f2tf32(qv.x * 0.125f), f2tf32(qv.y * 0.125f),
                                  f2tf32(qv.z * 0.125f), f2tf32(qv.w * 0.125f));
            *(uint4*)&Qs[row][dbas + u * 4] = tv;
        }
    }

    float4 o[8];
#pragma unroll
    for (int nt = 0; nt < 8; nt++) o[nt] = make_float4(0.f, 0.f, 0.f, 0.f);
    float m0 = -1e30f, m1 = -1e30f, l0 = 0.f, l1 = 0.f;

    for (int kt = 0; kt < Tt / 64; kt++) {
        __syncthreads();   // prev iter done reading Ps(=Kn)/Vt; Qs visible (iter 0)
        {
            int key  = tid & 63;
            int dbas = (tid >> 6) * 32;
            const float* kr = Kh + (size_t)(kt * 64 + key) * Dd + dbas;
            const float* vr = Vh + (size_t)(kt * 64 + key) * Dd + dbas;
#pragma unroll
            for (int u = 0; u < 8; u++) {
                float4 kv = *(const float4*)(kr + u * 4);
                uint4 tk = make_uint4(f2tf32(kv.x), f2tf32(kv.y), f2tf32(kv.z), f2tf32(kv.w));
                *(uint4*)&Kn[key][dbas + u * 4] = tk;
                float4 vv = *(const float4*)(vr + u * 4);
                Vt[dbas + u * 4 + 0][key] = f2tf32(vv.x);
                Vt[dbas + u * 4 + 1][key] = f2tf32(vv.y);
                Vt[dbas + u * 4 + 2][key] = f2tf32(vv.z);
                Vt[dbas + u * 4 + 3][key] = f2tf32(vv.w);
            }
        }
        __syncthreads();

        // ---- S = (Q*scale) @ K^T  (A from Qs, B[k=d][n=key] from Kn[n][k]) ----
        float4 s[8];
#pragma unroll
        for (int nt = 0; nt < 8; nt++) s[nt] = make_float4(0.f, 0.f, 0.f, 0.f);
#pragma unroll
        for (int ks = 0; ks < 8; ks++) {
            const int kb = ks * 8;
            uint32_t a0 = Qs[q0 + gid][kb + tig];
            uint32_t a1 = Qs[q0 + gid + 8][kb + tig];
            uint32_t a2 = Qs[q0 + gid][kb + tig + 4];
            uint32_t a3 = Qs[q0 + gid + 8][kb + tig + 4];
#pragma unroll
            for (int nt = 0; nt < 8; nt++) {
                uint32_t b0 = Kn[nt * 8 + gid][kb + tig];
                uint32_t b1 = Kn[nt * 8 + gid][kb + tig + 4];
                mma_tf32(s[nt], a0, a1, a2, a3, b0, b1);
            }
        }

        // ---- online softmax (rows gid / gid+8; reduce over tig lanes) ----
        float mx0 = -1e30f, mx1 = -1e30f;
#pragma unroll
        for (int nt = 0; nt < 8; nt++) {
            mx0 = fmaxf(mx0, fmaxf(s[nt].x, s[nt].y));
            mx1 = fmaxf(mx1, fmaxf(s[nt].z, s[nt].w));
        }
        mx0 = fmaxf(mx0, __shfl_xor_sync(0xffffffffu, mx0, 1));
        mx0 = fmaxf(mx0, __shfl_xor_sync(0xffffffffu, mx0, 2));
        mx1 = fmaxf(mx1, __shfl_xor_sync(0xffffffffu, mx1, 1));
        mx1 = fmaxf(mx1, __shfl_xor_sync(0xffffffffu, mx1, 2));
        float mn0 = fmaxf(m0, mx0);
        float mn1 = fmaxf(m1, mx1);
        float c0 = __expf(m0 - mn0);
        float c1 = __expf(m1 - mn1);
        float sum0 = 0.f, sum1 = 0.f;
#pragma unroll
        for (int nt = 0; nt < 8; nt++) {
            s[nt].x = __expf(s[nt].x - mn0);
            s[nt].y = __expf(s[nt].y - mn0);
            s[nt].z = __expf(s[nt].z - mn1);
            s[nt].w = __expf(s[nt].w - mn1);
            sum0 += s[nt].x + s[nt].y;
            sum1 += s[nt].z + s[nt].w;
        }
        sum0 += __shfl_xor_sync(0xffffffffu, sum0, 1);
        sum0 += __shfl_xor_sync(0xffffffffu, sum0, 2);
        sum1 += __shfl_xor_sync(0xffffffffu, sum1, 1);
        sum1 += __shfl_xor_sync(0xffffffffu, sum1, 2);
        l0 = l0 * c0 + sum0;  m0 = mn0;
        l1 = l1 * c1 + sum1;  m1 = mn1;
#pragma unroll
        for (int nt = 0; nt < 8; nt++) {
            o[nt].x *= c0; o[nt].y *= c0;
            o[nt].z *= c1; o[nt].w *= c1;
        }

        __syncthreads();   // all warps done reading Kn before overwriting with P

        // ---- store P (tf32) into Ps[q][key] (own warp rows only) ----
#pragma unroll
        for (int nt = 0; nt < 8; nt++) {
            int c = nt * 8 + 2 * tig;
            *(uint2*)&Ps[q0 + gid][c]     = make_uint2(f2tf32(s[nt].x), f2tf32(s[nt].y));
            *(uint2*)&Ps[q0 + gid + 8][c] = make_uint2(f2tf32(s[nt].z), f2tf32(s[nt].w));
        }
        __syncwarp();

        // ---- O += P @ V  (A from Ps, B[k=key][n=d] from Vt[n][k]) ----
#pragma unroll
        for (int ks = 0; ks < 8; ks++) {
            const int kb = ks * 8;
            uint32_t a0 = Ps[q0 + gid][kb + tig];
            uint32_t a1 = Ps[q0 + gid + 8][kb + tig];
            uint32_t a2 = Ps[q0 + gid][kb + tig + 4];
            uint32_t a3 = Ps[q0 + gid + 8][kb + tig + 4];
#pragma unroll
            for (int nt = 0; nt < 8; nt++) {
                uint32_t b0 = Vt[nt * 8 + gid][kb + tig];
                uint32_t b1 = Vt[nt * 8 + gid][kb + tig + 4];
                mma_tf32(o[nt], a0, a1, a2, a3, b0, b1);
            }
        }
    }

    // write out [b, t, h*64 + d]
    float inv0 = 1.f / l0;
    float inv1 = 1.f / l1;
    int t0 = qt * 64 + q0 + gid;
    int t1 = t0 + 8;
#pragma unroll
    for (int nt = 0; nt < 8; nt++) {
        int col = h * Dd + nt * 8 + 2 * tig;
        *(float2*)(AO + (size_t)(b * Tt + t0) * Cc + col) =
            make_float2(o[nt].x * inv0, o[nt].y * inv0);
        *(float2*)(AO + (size_t)(b * Tt + t1) * Cc + col) =
            make_float2(o[nt].z * inv1, o[nt].w * inv1);
    }
}

// ---------------- launch ----------------
extern "C" void kernel_launch(void* const* d_in, const int* in_sizes, int n_in,
                              void* d_out, int out_size)
{
    const float* x      = (const float*)d_in[0];   // [4,2048,1024]
    const float* qkv_w  = (const float*)d_in[1];   // [3072,1024]
    const float* qkv_b  = (const float*)d_in[2];   // [3072]
    const float* proj_w = (const float*)d_in[3];   // [1024,1024]
    const float* proj_b = (const float*)d_in[4];   // [1024]
    float* out = (float*)d_out;                    // [4,2048,1024]

    float *p_qkv, *p_q, *p_k, *p_v, *p_ao, *p_cs;
    cudaGetSymbolAddress((void**)&p_qkv, g_qkv);
    cudaGetSymbolAddress((void**)&p_q,   g_q);
    cudaGetSymbolAddress((void**)&p_k,   g_k);
    cudaGetSymbolAddress((void**)&p_v,   g_v);
    cudaGetSymbolAddress((void**)&p_ao,  g_ao);
    cudaGetSymbolAddress((void**)&p_cs,  g_cs);

    const int flash_smem = 3 * 64 * FS * 4;   // 52224 B
    cudaFuncSetAttribute(flash_mma_kernel,
                         cudaFuncAttributeMaxDynamicSharedMemorySize, flash_smem);

    // 1) RoPE table
    rope_table_kernel<<<(Tt * NHALF + 255) / 256, 256>>>(p_cs);

    // 2) QKV GEMM: [8192,3072] = x @ qkv_w^T + qkv_b
    {
        dim3 grid(3 * Cc / 128, (Bb * Tt) / 128);
        mma_gemm_nt_bias<<<grid, 256>>>(x, qkv_w, qkv_b, p_qkv,
                                        Bb * Tt, 3 * Cc, Cc);
    }

    // 3) RoPE + scatter to [b,h,t,d]
    rope_scatter_kernel<<<(Bb * Tt * Hh * NHALF) / 256, 256>>>(
        p_qkv, p_cs, p_q, p_k, p_v);

    // 4) flash attention (tf32 mma)
    {
        dim3 grid(Tt / 64, Bb * Hh);
        flash_mma_kernel<<<grid, 128, flash_smem>>>(p_q, p_k, p_v, p_ao);
    }

    // 5) proj GEMM: out = ao @ proj_w^T + proj_b
    {
        dim3 grid(Cc / 128, (Bb * Tt) / 128);
        mma_gemm_nt_bias<<<grid, 256>>>(p_ao, proj_w, proj_b, out,
                                        Bb * Tt, Cc, Cc);
    }
}

// round 4
// speedup vs baseline: 4.0550x; 1.7563x over previous
#include <cuda_runtime.h>
#include <math.h>
#include <stdint.h>

// Problem constants (fixed by the reference)
#define Bb 4
#define Tt 2048
#define Cc 1024
#define Hh 16
#define Dd 64
#define NHALF 32   // Dd/2
#define NKT (Tt/64)

// ---------------- scratch (device globals; no allocs allowed) ----------------
__device__ float g_qkv[(size_t)Bb * Tt * 3 * Cc];      // [b,t,3,h,d] raw qkv+bias (fp32)
__device__ float g_q  [(size_t)Bb * Hh * Tt * Dd];     // [b,h,t,d] rope'd, tf32 bits, pre-scaled
__device__ float g_k  [(size_t)Bb * Hh * Tt * Dd];     // [b,h,t,d] rope'd, tf32 bits
__device__ float g_vT [(size_t)Bb * Hh * Dd * Tt];     // [b,h,d,t] transposed V, tf32 bits
__device__ float g_ao [(size_t)Bb * Tt * Cc];          // attention out, tf32 bits
__device__ float g_cs [Tt * NHALF * 2];                // interleaved cos,sin
__device__ float g_xr [(size_t)Bb * Tt * Cc];          // x rounded to tf32
__device__ float g_wq [(size_t)3 * Cc * Cc];           // qkv_w rounded
__device__ float g_wp [(size_t)Cc * Cc];               // proj_w rounded

// ---------------- helpers ----------------
__device__ __forceinline__ uint32_t f2tf32(float f) {
    uint32_t r;
    asm("cvt.rna.tf32.f32 %0, %1;" : "=r"(r) : "f"(f));
    return r;
}

__device__ __forceinline__ void mma_tf32(float4& d,
    uint32_t a0, uint32_t a1, uint32_t a2, uint32_t a3,
    uint32_t b0, uint32_t b1)
{
    asm volatile(
        "mma.sync.aligned.m16n8k8.row.col.f32.tf32.tf32.f32 "
        "{%0,%1,%2,%3}, {%4,%5,%6,%7}, {%8,%9}, {%0,%1,%2,%3};\n"
        : "+f"(d.x), "+f"(d.y), "+f"(d.z), "+f"(d.w)
        : "r"(a0), "r"(a1), "r"(a2), "r"(a3), "r"(b0), "r"(b1));
}

__device__ __forceinline__ void ldsm4(uint32_t& r0, uint32_t& r1,
                                      uint32_t& r2, uint32_t& r3, uint32_t addr)
{
    asm volatile("ldmatrix.sync.aligned.m8n8.x4.shared.b16 {%0,%1,%2,%3}, [%4];"
        : "=r"(r0), "=r"(r1), "=r"(r2), "=r"(r3) : "r"(addr));
}

__device__ __forceinline__ void cp16(uint32_t dst, const void* src) {
    asm volatile("cp.async.cg.shared.global [%0], [%1], 16;" :: "r"(dst), "l"(src));
}
#define CP_COMMIT() asm volatile("cp.async.commit_group;" ::: "memory")
#define CP_WAIT(n)  asm volatile("cp.async.wait_group %0;" :: "n"(n) : "memory")

// ---------------- RoPE table ----------------
__global__ void rope_table_kernel(float* cs) {
    int idx = blockIdx.x * blockDim.x + threadIdx.x;
    if (idx >= Tt * NHALF) return;
    int t = idx >> 5;
    int j = idx & 31;
    double freq  = pow(40.0, (double)j / 31.0);
    double theta = 2.0 * 3.14159265358979323846 * ((double)t / (double)Tt) * freq;
    cs[idx * 2 + 0] = (float)cos(theta);
    cs[idx * 2 + 1] = (float)sin(theta);
}

// ---------------- tf32 rounding prep ----------------
__global__ void tf32_round4(const float* __restrict__ s, float* __restrict__ d, int n4) {
    int i = blockIdx.x * blockDim.x + threadIdx.x;
    if (i >= n4) return;
    float4 v = ((const float4*)s)[i];
    uint4 u = make_uint4(f2tf32(v.x), f2tf32(v.y), f2tf32(v.z), f2tf32(v.w));
    ((uint4*)d)[i] = u;
}

// ---------------- GEMM v2: C[M,N] = A[M,K] @ B[N,K]^T + bias[N] ----------------
// A,B pre-rounded tf32 bits. BM=BN=128, BK=32, 256 thr (8 warps 2x4, warp 64x32).
// cp.async 2-stage pipeline + ldmatrix fragments. Smem rows stride 36 words.
#define GS 36
__global__ void __launch_bounds__(256, 2) gemm_v2(
    const float* __restrict__ A, const float* __restrict__ B,
    const float* __restrict__ bias, float* __restrict__ C,
    int M, int N, int K)
{
    extern __shared__ uint32_t sg[];
    const uint32_t sbase = (uint32_t)__cvta_generic_to_shared(sg);
    // word offsets: As[2][128][36], Bs[2][128][36]
    const int ASO = 0, BSO = 2 * 128 * GS;

    const int tid  = threadIdx.x;
    const int lane = tid & 31;
    const int warp = tid >> 5;
    const int wr   = warp >> 2;
    const int wc   = warp & 3;
    const int gid  = lane >> 2;
    const int tig  = lane & 3;
    const int bm   = blockIdx.y * 128;
    const int bn   = blockIdx.x * 128;

    const float* Ab = A + (size_t)bm * K;
    const float* Bp = B + (size_t)bn * K;

    // ldmatrix lane geometry
    const int arow = ((lane >> 3) & 1) * 8 + (lane & 7);
    const int acol = ((lane >> 4) & 1) * 4;
    const int brow = ((lane >> 4) & 1) * 8 + (lane & 7);
    const int bcol = ((lane >> 3) & 1) * 4;
    const uint32_t aoffA = (uint32_t)((ASO + (wr * 64 + arow) * GS + acol) * 4);
    const uint32_t aoffB = (uint32_t)((BSO + (wc * 32 + brow) * GS + bcol) * 4);  // FIX: add BSO

    float4 acc[4][4];
#pragma unroll
    for (int i = 0; i < 4; i++)
#pragma unroll
        for (int j = 0; j < 4; j++) acc[i][j] = make_float4(0.f, 0.f, 0.f, 0.f);

    // stage issue: rows 0..127, 8 chunks of 16B per row (BK=32 floats)
#define GEMM_ISSUE(k0, soff)                                                        \
    {                                                                               \
        _Pragma("unroll")                                                           \
        for (int ii = 0; ii < 4; ii++) {                                            \
            int cid = tid + ii * 256; int row = cid >> 3; int ch = cid & 7;         \
            cp16(sbase + (uint32_t)(((soff) + ASO + row * GS + ch * 4) * 4),        \
                 Ab + (size_t)row * K + (k0) + ch * 4);                             \
        }                                                                           \
        _Pragma("unroll")                                                           \
        for (int ii = 0; ii < 4; ii++) {                                            \
            int cid = tid + ii * 256; int row = cid >> 3; int ch = cid & 7;         \
            cp16(sbase + (uint32_t)(((soff) + BSO + row * GS + ch * 4) * 4),        \
                 Bp + (size_t)row * K + (k0) + ch * 4);                             \
        }                                                                           \
    }

    GEMM_ISSUE(0, 0);
    CP_COMMIT();

    const int NIT = K / 32;
    int soff = 0;
    for (int it = 0; it < NIT; it++) {
        CP_WAIT(0);
        __syncthreads();
        int nsoff = soff ^ (128 * GS);
        if (it + 1 < NIT) { GEMM_ISSUE((it + 1) * 32, nsoff); }
        CP_COMMIT();

        const uint32_t baseA = sbase + (uint32_t)(soff * 4) + aoffA;
        const uint32_t baseB = sbase + (uint32_t)(soff * 4) + aoffB;
#pragma unroll
        for (int ks = 0; ks < 4; ks++) {
            uint32_t a[4][4];
#pragma unroll
            for (int mt = 0; mt < 4; mt++)
                ldsm4(a[mt][0], a[mt][1], a[mt][2], a[mt][3],
                      baseA + mt * (16 * GS * 4) + ks * 32);
#pragma unroll
            for (int ntp = 0; ntp < 2; ntp++) {
                uint32_t b0, b1, b2, b3;
                ldsm4(b0, b1, b2, b3, baseB + ntp * (16 * GS * 4) + ks * 32);
#pragma unroll
                for (int mt = 0; mt < 4; mt++) {
                    mma_tf32(acc[mt][2 * ntp],     a[mt][0], a[mt][1], a[mt][2], a[mt][3], b0, b1);
                    mma_tf32(acc[mt][2 * ntp + 1], a[mt][0], a[mt][1], a[mt][2], a[mt][3], b2, b3);
                }
            }
        }
        soff = nsoff;
    }

    // epilogue: bias + store (fp32)
#pragma unroll
    for (int nt = 0; nt < 4; nt++) {
        int c = bn + wc * 32 + nt * 8 + 2 * tig;
        float bx = bias[c];
        float by = bias[c + 1];
#pragma unroll
        for (int mt = 0; mt < 4; mt++) {
            int r0 = bm + wr * 64 + mt * 16 + gid;
            *(float2*)(C + (size_t)r0 * N + c) =
                make_float2(acc[mt][nt].x + bx, acc[mt][nt].y + by);
            *(float2*)(C + (size_t)(r0 + 8) * N + c) =
                make_float2(acc[mt][nt].z + bx, acc[mt][nt].w + by);
        }
    }
}

// ---------------- RoPE apply + scatter (writes tf32 bits; V transposed) ----------------
__global__ void rope_scatter_v2(const float* __restrict__ QKV,
                                const float* __restrict__ cs,
                                float* __restrict__ Q,
                                float* __restrict__ K,
                                float* __restrict__ VT)
{
    int idx = blockIdx.x * blockDim.x + threadIdx.x;
    if (idx >= Bb * Tt * Hh * NHALF) return;
    int j = idx & 31;
    int h = (idx >> 5) & 15;
    int t = (idx >> 9) & 2047;
    int b = idx >> 20;

    float co = cs[(t * 32 + j) * 2 + 0];
    float si = cs[(t * 32 + j) * 2 + 1];

    size_t base = ((size_t)(b * Tt + t)) * (3 * Cc) + h * Dd + j;
    float q1 = QKV[base];
    float q2 = QKV[base + 32];
    float k1 = QKV[base + Cc];
    float k2 = QKV[base + Cc + 32];
    float v1 = QKV[base + 2 * Cc];
    float v2 = QKV[base + 2 * Cc + 32];

    size_t ob = ((size_t)((b * Hh + h) * Tt + t)) * Dd + j;
    Q[ob]      = __uint_as_float(f2tf32(0.125f * (q1 * co - q2 * si)));
    Q[ob + 32] = __uint_as_float(f2tf32(0.125f * (q1 * si + q2 * co)));
    K[ob]      = __uint_as_float(f2tf32(k1 * co - k2 * si));
    K[ob + 32] = __uint_as_float(f2tf32(k1 * si + k2 * co));

    size_t vb = ((size_t)((b * Hh + h) * Dd + j)) * Tt + t;
    VT[vb]                    = __uint_as_float(f2tf32(v1));
    VT[vb + (size_t)32 * Tt]  = __uint_as_float(f2tf32(v2));
}

// ---------------- Flash attention v2: 128q x 64k tiles, cp.async + ldmatrix ----------------
// 256 threads = 8 warps, each warp owns 16 q-rows. Inputs pre-tf32.
// smem (words, stride FS=68): Qs[128][68] | Kn[64][68] | Vt[64][68] | Ps[128][68]
#define FS 68
__global__ void __launch_bounds__(256, 2) flash_v2(
    const float* __restrict__ Qg, const float* __restrict__ Kg,
    const float* __restrict__ VTg, float* __restrict__ AO)
{
    extern __shared__ uint32_t sm[];
    const uint32_t sbase = (uint32_t)__cvta_generic_to_shared(sm);
    const int QSO = 0;
    const int KNO = 128 * FS;
    const int VTO = KNO + 64 * FS;
    const int PSO = VTO + 64 * FS;

    const int tid  = threadIdx.x;
    const int lane = tid & 31;
    const int warp = tid >> 5;
    const int gid  = lane >> 2;
    const int tig  = lane & 3;
    const int q0   = warp * 16;
    const int qt   = blockIdx.x;
    const int bh   = blockIdx.y;
    const int b    = bh >> 4;
    const int h    = bh & 15;

    const float* Qh = Qg  + (size_t)bh * Tt * Dd + (size_t)qt * 128 * Dd;
    const float* Kh = Kg  + (size_t)bh * Tt * Dd;
    const float* Vh = VTg + (size_t)bh * Dd * Tt;

    // ldmatrix lane geometry
    const int arow = ((lane >> 3) & 1) * 8 + (lane & 7);
    const int acol = ((lane >> 4) & 1) * 4;
    const int brow = ((lane >> 4) & 1) * 8 + (lane & 7);
    const int bcol = ((lane >> 3) & 1) * 4;
    const uint32_t aQ = sbase + (uint32_t)((QSO + (q0 + arow) * FS + acol) * 4);
    const uint32_t aP = sbase + (uint32_t)((PSO + (q0 + arow) * FS + acol) * 4);
    const uint32_t aK = sbase + (uint32_t)((KNO + brow * FS + bcol) * 4);
    const uint32_t aV = sbase + (uint32_t)((VTO + brow * FS + bcol) * 4);

    // ---- prologue: Q tile + K(0) (group 0), V(0) (group 1) ----
#pragma unroll
    for (int i = 0; i < 8; i++) {
        int cid = tid + i * 256; int row = cid >> 4; int ch = cid & 15;
        cp16(sbase + (uint32_t)((QSO + row * FS + ch * 4) * 4),
             Qh + (size_t)row * Dd + ch * 4);
    }
#pragma unroll
    for (int i = 0; i < 4; i++) {
        int cid = tid + i * 256; int row = cid >> 4; int ch = cid & 15;
        cp16(sbase + (uint32_t)((KNO + row * FS + ch * 4) * 4),
             Kh + (size_t)row * Dd + ch * 4);
    }
    CP_COMMIT();
#pragma unroll
    for (int i = 0; i < 4; i++) {
        int cid = tid + i * 256; int row = cid >> 4; int ch = cid & 15;
        cp16(sbase + (uint32_t)((VTO + row * FS + ch * 4) * 4),
             Vh + (size_t)row * Tt + ch * 4);
    }
    CP_COMMIT();

    float4 o[8];
#pragma unroll
    for (int nt = 0; nt < 8; nt++) o[nt] = make_float4(0.f, 0.f, 0.f, 0.f);
    float m0 = -1e30f, m1 = -1e30f, l0 = 0.f, l1 = 0.f;

    for (int kt = 0; kt < NKT; kt++) {
        CP_WAIT(1);          // Q + K(kt) ready (V(kt) may still fly)
        __syncthreads();

        // ---- S = Q @ K^T ----
        float4 s[8];
#pragma unroll
        for (int nt = 0; nt < 8; nt++) s[nt] = make_float4(0.f, 0.f, 0.f, 0.f);
#pragma unroll
        for (int ks = 0; ks < 8; ks++) {
            uint32_t a0, a1, a2, a3;
            ldsm4(a0, a1, a2, a3, aQ + ks * 32);
#pragma unroll
            for (int ntp = 0; ntp < 4; ntp++) {
                uint32_t b0, b1, b2, b3;
                ldsm4(b0, b1, b2, b3, aK + ntp * (16 * FS * 4) + ks * 32);
                mma_tf32(s[2 * ntp],     a0, a1, a2, a3, b0, b1);
                mma_tf32(s[2 * ntp + 1], a0, a1, a2, a3, b2, b3);
            }
        }
        __syncthreads();     // all warps done reading Kn

        // prefetch K(kt+1)
        if (kt + 1 < NKT) {
            const float* Kn2 = Kh + (size_t)(kt + 1) * 64 * Dd;
#pragma unroll
            for (int i = 0; i < 4; i++) {
                int cid = tid + i * 256; int row = cid >> 4; int ch = cid & 15;
                cp16(sbase + (uint32_t)((KNO + row * FS + ch * 4) * 4),
                     Kn2 + (size_t)row * Dd + ch * 4);
            }
        }
        CP_COMMIT();

        // ---- online softmax ----
        float mx0 = -1e30f, mx1 = -1e30f;
#pragma unroll
        for (int nt = 0; nt < 8; nt++) {
            mx0 = fmaxf(mx0, fmaxf(s[nt].x, s[nt].y));
            mx1 = fmaxf(mx1, fmaxf(s[nt].z, s[nt].w));
        }
        mx0 = fmaxf(mx0, __shfl_xor_sync(0xffffffffu, mx0, 1));
        mx0 = fmaxf(mx0, __shfl_xor_sync(0xffffffffu, mx0, 2));
        mx1 = fmaxf(mx1, __shfl_xor_sync(0xffffffffu, mx1, 1));
        mx1 = fmaxf(mx1, __shfl_xor_sync(0xffffffffu, mx1, 2));
        float mn0 = fmaxf(m0, mx0);
        float mn1 = fmaxf(m1, mx1);
        float c0 = __expf(m0 - mn0);
        float c1 = __expf(m1 - mn1);
        float sum0 = 0.f, sum1 = 0.f;
#pragma unroll
        for (int nt = 0; nt < 8; nt++) {
            s[nt].x = __expf(s[nt].x - mn0);
            s[nt].y = __expf(s[nt].y - mn0);
            s[nt].z = __expf(s[nt].z - mn1);
            s[nt].w = __expf(s[nt].w - mn1);
            sum0 += s[nt].x + s[nt].y;
            sum1 += s[nt].z + s[nt].w;
        }
        sum0 += __shfl_xor_sync(0xffffffffu, sum0, 1);
        sum0 += __shfl_xor_sync(0xffffffffu, sum0, 2);
        sum1 += __shfl_xor_sync(0xffffffffu, sum1, 1);
        sum1 += __shfl_xor_sync(0xffffffffu, sum1, 2);
        l0 = l0 * c0 + sum0;  m0 = mn0;
        l1 = l1 * c1 + sum1;  m1 = mn1;
#pragma unroll
        for (int nt = 0; nt < 8; nt++) {
            o[nt].x *= c0; o[nt].y *= c0;
            o[nt].z *= c1; o[nt].w *= c1;
        }

        // ---- store P (tf32) into Ps[q][key] ----
#pragma unroll
        for (int nt = 0; nt < 8; nt++) {
            int c = nt * 8 + 2 * tig;
            *(uint2*)&sm[PSO + (q0 + gid) * FS + c] =
                make_uint2(f2tf32(s[nt].x), f2tf32(s[nt].y));
            *(uint2*)&sm[PSO + (q0 + gid + 8) * FS + c] =
                make_uint2(f2tf32(s[nt].z), f2tf32(s[nt].w));
        }

        CP_WAIT(1);          // V(kt) ready (pending: K(kt+1))
        __syncthreads();     // also publishes P stores

        // ---- O += P @ V ----
#pragma unroll
        for (int ks = 0; ks < 8; ks++) {
            uint32_t a0, a1, a2, a3;
            ldsm4(a0, a1, a2, a3, aP + ks * 32);
#pragma unroll
            for (int ntp = 0; ntp < 4; ntp++) {
                uint32_t b0, b1, b2, b3;
                ldsm4(b0, b1, b2, b3, aV + ntp * (16 * FS * 4) + ks * 32);
                mma_tf32(o[2 * ntp],     a0, a1, a2, a3, b0, b1);
                mma_tf32(o[2 * ntp + 1], a0, a1, a2, a3, b2, b3);
            }
        }
        __syncthreads();     // all warps done reading Vt

        // issue V(kt+1)
        if (kt + 1 < NKT) {
            const float* Vn2 = Vh + (size_t)(kt + 1) * 64;
#pragma unroll
            for (int i = 0; i < 4; i++) {
                int cid = tid + i * 256; int row = cid >> 4; int ch = cid & 15;
                cp16(sbase + (uint32_t)((VTO + row * FS + ch * 4) * 4),
                     Vn2 + (size_t)row * Tt + ch * 4);
            }
        }
        CP_COMMIT();
    }

    // ---- epilogue: AO = O / l, stored as tf32 bits (input to proj GEMM) ----
    float inv0 = 1.f / l0;
    float inv1 = 1.f / l1;
    int t0 = qt * 128 + q0 + gid;
    int t1 = t0 + 8;
#pragma unroll
    for (int nt = 0; nt < 8; nt++) {
        int col = h * Dd + nt * 8 + 2 * tig;
        *(uint2*)(AO + (size_t)(b * Tt + t0) * Cc + col) =
            make_uint2(f2tf32(o[nt].x * inv0), f2tf32(o[nt].y * inv0));
        *(uint2*)(AO + (size_t)(b * Tt + t1) * Cc + col) =
            make_uint2(f2tf32(o[nt].z * inv1), f2tf32(o[nt].w * inv1));
    }
}

// ---------------- launch ----------------
extern "C" void kernel_launch(void* const* d_in, const int* in_sizes, int n_in,
                              void* d_out, int out_size)
{
    const float* x      = (const float*)d_in[0];   // [4,2048,1024]
    const float* qkv_w  = (const float*)d_in[1];   // [3072,1024]
    const float* qkv_b  = (const float*)d_in[2];   // [3072]
    const float* proj_w = (const float*)d_in[3];   // [1024,1024]
    const float* proj_b = (const float*)d_in[4];   // [1024]
    float* out = (float*)d_out;                    // [4,2048,1024]

    float *p_qkv, *p_q, *p_k, *p_vT, *p_ao, *p_cs, *p_xr, *p_wq, *p_wp;
    cudaGetSymbolAddress((void**)&p_qkv, g_qkv);
    cudaGetSymbolAddress((void**)&p_q,   g_q);
    cudaGetSymbolAddress((void**)&p_k,   g_k);
    cudaGetSymbolAddress((void**)&p_vT,  g_vT);
    cudaGetSymbolAddress((void**)&p_ao,  g_ao);
    cudaGetSymbolAddress((void**)&p_cs,  g_cs);
    cudaGetSymbolAddress((void**)&p_xr,  g_xr);
    cudaGetSymbolAddress((void**)&p_wq,  g_wq);
    cudaGetSymbolAddress((void**)&p_wp,  g_wp);

    const int gemm_smem  = 4 * 128 * GS * 4;       // 73728 B
    const int flash_smem = (128 * FS + 64 * FS + 64 * FS + 128 * FS) * 4;  // 104448 B
    cudaFuncSetAttribute(gemm_v2,
                         cudaFuncAttributeMaxDynamicSharedMemorySize, gemm_smem);
    cudaFuncSetAttribute(flash_v2,
                         cudaFuncAttributeMaxDynamicSharedMemorySize, flash_smem);

    // 1) RoPE table + tf32 prep
    rope_table_kernel<<<(Tt * NHALF + 255) / 256, 256>>>(p_cs);
    tf32_round4<<<(Bb * Tt * Cc / 4 + 255) / 256, 256>>>(x, p_xr, Bb * Tt * Cc / 4);
    tf32_round4<<<(3 * Cc * Cc / 4 + 255) / 256, 256>>>(qkv_w, p_wq, 3 * Cc * Cc / 4);
    tf32_round4<<<(Cc * Cc / 4 + 255) / 256, 256>>>(proj_w, p_wp, Cc * Cc / 4);

    // 2) QKV GEMM: [8192,3072] = xr @ wq^T + qkv_b
    {
        dim3 grid(3 * Cc / 128, (Bb * Tt) / 128);
        gemm_v2<<<grid, 256, gemm_smem>>>(p_xr, p_wq, qkv_b, p_qkv,
                                          Bb * Tt, 3 * Cc, Cc);
    }

    // 3) RoPE + scatter (tf32 outputs, V transposed)
    rope_scatter_v2<<<(Bb * Tt * Hh * NHALF) / 256, 256>>>(
        p_qkv, p_cs, p_q, p_k, p_vT);

    // 4) flash attention
    {
        dim3 grid(Tt / 128, Bb * Hh);
        flash_v2<<<grid, 256, flash_smem>>>(p_q, p_k, p_vT, p_ao);
    }

    // 5) proj GEMM: out = ao @ wp^T + proj_b
    {
        dim3 grid(Cc / 128, (Bb * Tt) / 128);
        gemm_v2<<<grid, 256, gemm_smem>>>(p_ao, p_wp, proj_b, out,
                                          Bb * Tt, Cc, Cc);
    }
}